// round 6
// baseline (speedup 1.0000x reference)
#include <cuda_runtime.h>
#include <cuda_fp16.h>

#define Eq 1024
#define NH 16
#define DH 64
#define NB 4
#define SL 2048

// Scratch (__device__ globals; alloc-free rule). All fp16 packed as u32 pairs.
__device__ unsigned g_qc[NB * SL * Eq / 2];      // fp16(query)
__device__ unsigned g_kvc[NB * SL * Eq / 2];     // fp16(key_value)
__device__ unsigned g_wq[Eq * Eq / 2], g_wk[Eq * Eq / 2];
__device__ unsigned g_wv[Eq * Eq / 2], g_wo[Eq * Eq / 2];
__device__ unsigned g_q[NB * NH * SL * DH / 2];  // [B,H,S,HD] fp16
__device__ unsigned g_k[NB * NH * SL * DH / 2];  // [B,H,S,HD] fp16
__device__ unsigned g_vt[NB * NH * SL * DH / 2]; // [B,H,HD,S] fp16 (transposed!)
__device__ unsigned g_ctx[NB * SL * Eq / 2];     // [B,S,E] fp16

__device__ __forceinline__ unsigned pkh2(float a, float b) {
    __half2 h = __floats2half2_rn(a, b);
    return *(unsigned*)&h;
}

__device__ __forceinline__ void mma16(float* c, const unsigned* a, const unsigned* b) {
    asm volatile(
        "mma.sync.aligned.m16n8k16.row.col.f32.f16.f16.f32 "
        "{%0,%1,%2,%3}, {%4,%5,%6,%7}, {%8,%9}, {%0,%1,%2,%3};"
        : "+f"(c[0]), "+f"(c[1]), "+f"(c[2]), "+f"(c[3])
        : "r"(a[0]), "r"(a[1]), "r"(a[2]), "r"(a[3]), "r"(b[0]), "r"(b[1]));
}

__device__ __forceinline__ void cp16(unsigned smem_u32, const void* gptr) {
    asm volatile("cp.async.cg.shared.global [%0], [%1], 16;" :: "r"(smem_u32), "l"(gptr));
}
#define CP_COMMIT() asm volatile("cp.async.commit_group;")
#define CP_WAIT0()  asm volatile("cp.async.wait_group 0;")

// ---------------------------------------------------------------------------
// fp32 -> fp16-packed converter
// ---------------------------------------------------------------------------
__global__ void cvt_f16(const float4* __restrict__ src, uint2* __restrict__ dst, int n4) {
    for (int i = blockIdx.x * blockDim.x + threadIdx.x; i < n4; i += gridDim.x * blockDim.x) {
        float4 s = src[i];
        dst[i] = make_uint2(pkh2(s.x, s.y), pkh2(s.z, s.w));
    }
}

// ---------------------------------------------------------------------------
// fp16 GEMM: out = A @ W^T + bias. A,W fp16-packed u32, K-major (512 u32/row).
// 128x128x32 tile, 256 thr (8 warps 4x2), warp 32x64. cp.async 2-stage.
// MODE 0: [B,H,S,HD] fp16; MODE 1: flat fp32; MODE 2: [B,H,HD,S] fp16 transposed.
// ---------------------------------------------------------------------------
#define GP 20  // u32 pitch per row (16 used)

template <int MODE>
__global__ __launch_bounds__(256, 2) void gemm_f16(
    const unsigned* __restrict__ A, const unsigned* __restrict__ W,
    const float* __restrict__ bias, float* __restrict__ out)
{
    __shared__ unsigned As[2][128 * GP];
    __shared__ unsigned Bs[2][128 * GP];

    const int tid = threadIdx.x;
    const int m0 = blockIdx.y * 128, n0 = blockIdx.x * 128;
    const int w = tid >> 5, lane = tid & 31;
    const int wm = w >> 1, wn = w & 1;
    const int g = lane >> 2, q4 = lane & 3;

    // copy mapping: per stage per operand 512 chunks (128 rows x 4x16B)
    const int r0 = tid >> 2, r1 = r0 + 64;
    const int kq = (tid & 3) * 4;

    const unsigned sA = (unsigned)__cvta_generic_to_shared(&As[0][0]);
    const unsigned sB = (unsigned)__cvta_generic_to_shared(&Bs[0][0]);
    const unsigned stageBytes = 128 * GP * 4;

    float acc[2][8][4];
#pragma unroll
    for (int i = 0; i < 2; i++)
#pragma unroll
        for (int j = 0; j < 8; j++)
#pragma unroll
            for (int l = 0; l < 4; l++) acc[i][j][l] = 0.0f;

    auto issue = [&](int t) {
        const int s = t & 1;
        const int kb = t * 16 + kq;  // u32 col in gmem row
        cp16(sA + s * stageBytes + (r0 * GP + kq) * 4, A + (size_t)(m0 + r0) * 512 + kb);
        cp16(sA + s * stageBytes + (r1 * GP + kq) * 4, A + (size_t)(m0 + r1) * 512 + kb);
        cp16(sB + s * stageBytes + (r0 * GP + kq) * 4, W + (size_t)(n0 + r0) * 512 + kb);
        cp16(sB + s * stageBytes + (r1 * GP + kq) * 4, W + (size_t)(n0 + r1) * 512 + kb);
        CP_COMMIT();
    };

    issue(0);
    for (int t = 0; t < 32; t++) {
        CP_WAIT0();
        __syncthreads();
        if (t < 31) issue(t + 1);
        const unsigned* as = &As[t & 1][0];
        const unsigned* bs = &Bs[t & 1][0];
#pragma unroll
        for (int kb4 = 0; kb4 < 16; kb4 += 8) {  // two k16 blocks
            unsigned af[2][4], bf[8][2];
#pragma unroll
            for (int im = 0; im < 2; im++) {
                const int mr = wm * 32 + im * 16 + g;
                af[im][0] = as[mr * GP + kb4 + q4];
                af[im][1] = as[(mr + 8) * GP + kb4 + q4];
                af[im][2] = as[mr * GP + kb4 + q4 + 4];
                af[im][3] = as[(mr + 8) * GP + kb4 + q4 + 4];
            }
#pragma unroll
            for (int jn = 0; jn < 8; jn++) {
                const int nc = wn * 64 + jn * 8 + g;
                bf[jn][0] = bs[nc * GP + kb4 + q4];
                bf[jn][1] = bs[nc * GP + kb4 + q4 + 4];
            }
#pragma unroll
            for (int im = 0; im < 2; im++)
#pragma unroll
                for (int jn = 0; jn < 8; jn++)
                    mma16(acc[im][jn], af[im], bf[jn]);
        }
    }

#pragma unroll
    for (int im = 0; im < 2; im++) {
#pragma unroll
        for (int jn = 0; jn < 8; jn++) {
            const int gn = n0 + wn * 64 + jn * 8 + 2 * q4;
            const float2 bv = *(const float2*)(bias + gn);
#pragma unroll
            for (int h2 = 0; h2 < 2; h2++) {
                const int gm = m0 + wm * 32 + im * 16 + h2 * 8 + g;
                const float o0 = acc[im][jn][2 * h2] + bv.x;
                const float o1 = acc[im][jn][2 * h2 + 1] + bv.y;
                const int bb = gm >> 11, ss = gm & 2047;
                const int hh = gn >> 6, dd = gn & 63;
                if (MODE == 0) {
                    ((unsigned*)out)[(((size_t)(bb * NH + hh)) * SL + ss) * 32 + (dd >> 1)] =
                        pkh2(o0, o1);
                } else if (MODE == 2) {
                    __half* vt = (__half*)out;
                    vt[(((size_t)(bb * NH + hh)) * DH + dd) * SL + ss] = __float2half_rn(o0);
                    vt[(((size_t)(bb * NH + hh)) * DH + dd + 1) * SL + ss] = __float2half_rn(o1);
                } else {
                    *(float2*)(out + (size_t)gm * Eq + gn) = make_float2(o0, o1);
                }
            }
        }
    }
}

// ---------------------------------------------------------------------------
// Fused stablemax attention, fp16 m16n8k16, register-resident T (FA2 identity),
// register denominators, V^T gmem layout, cp.async double-buffered K/V.
// 8 warps x 16 q-rows, full n=64 per warp. One __syncthreads per kv tile.
// ---------------------------------------------------------------------------
#define AP 36  // u32 pitch for 64-half rows (32 used)
#define ATTN_SMEM_BYTES ((128 * AP + 4 * 64 * AP) * 4)

__global__ __launch_bounds__(256, 2) void attn_f16(
    const unsigned* __restrict__ qg, const unsigned* __restrict__ kg,
    const unsigned* __restrict__ vtg, unsigned* __restrict__ ctx)
{
    extern __shared__ unsigned sm[];
    unsigned* Qs = sm;                // [128][AP]
    unsigned* Ks = Qs + 128 * AP;     // [2][64][AP]
    unsigned* Vs = Ks + 2 * 64 * AP;  // [2][64][AP]  rows = dv, cols = kv halfs

    const int tid = threadIdx.x;
    const int wm = tid >> 5, lane = tid & 31;
    const int g = lane >> 2, q4 = lane & 3;
    const int bh = blockIdx.y, q0 = blockIdx.x * 128;
    const int r_lo = wm * 16 + g, r_hi = r_lo + 8;

    const unsigned* qb = qg + ((size_t)bh * SL + q0) * 32;
    const unsigned* kb = kg + (size_t)bh * SL * 32;
    const unsigned* vtb = vtg + (size_t)bh * DH * (SL / 2);  // [64 rows][1024 u32]

    const unsigned sQ = (unsigned)__cvta_generic_to_shared(Qs);
    const unsigned sK = (unsigned)__cvta_generic_to_shared(Ks);
    const unsigned sV = (unsigned)__cvta_generic_to_shared(Vs);
    const unsigned kvStage = 64 * AP * 4;

    auto issue_kv = [&](int t) {
        const int s = t & 1;
        const int kv0 = t * 64;
#pragma unroll
        for (int i = 0; i < 2; i++) {
            const int idx = tid + i * 256;  // 0..511
            const int row = idx >> 3, c = (idx & 7) * 4;
            cp16(sK + s * kvStage + (row * AP + c) * 4, kb + (size_t)(kv0 + row) * 32 + c);
            cp16(sV + s * kvStage + (row * AP + c) * 4, vtb + (size_t)row * 1024 + (kv0 >> 1) + c);
        }
        CP_COMMIT();
    };

    // Prologue: Q tile + first K/V
#pragma unroll
    for (int i = 0; i < 4; i++) {
        const int idx = tid + i * 256;  // 0..1023
        const int row = idx >> 3, c = (idx & 7) * 4;
        cp16(sQ + (row * AP + c) * 4, qb + (size_t)row * 32 + c);
    }
    issue_kv(0);
    CP_WAIT0();
    __syncthreads();

    float oacc[8][4];
#pragma unroll
    for (int j = 0; j < 8; j++)
#pragma unroll
        for (int l = 0; l < 4; l++) oacc[j][l] = 0.0f;
    float dlo = 0.0f, dhi = 0.0f;

    // Q fragments are tile-invariant: hoist
    unsigned qf[4][4];
#pragma unroll
    for (int kb4 = 0; kb4 < 4; kb4++) {
        qf[kb4][0] = Qs[r_lo * AP + kb4 * 8 + q4];
        qf[kb4][1] = Qs[r_hi * AP + kb4 * 8 + q4];
        qf[kb4][2] = Qs[r_lo * AP + kb4 * 8 + q4 + 4];
        qf[kb4][3] = Qs[r_hi * AP + kb4 * 8 + q4 + 4];
    }

    for (int t = 0; t < 32; t++) {
        const unsigned* ks_ = Ks + (t & 1) * 64 * AP;
        const unsigned* vs_ = Vs + (t & 1) * 64 * AP;
        if (t < 31) issue_kv(t + 1);

        // GEMM1: S(16m x 64n) = Q K^T, k = 64 (4 k16 blocks)
        float sacc[8][4];
#pragma unroll
        for (int j = 0; j < 8; j++)
#pragma unroll
            for (int l = 0; l < 4; l++) sacc[j][l] = 0.0f;

#pragma unroll
        for (int kb4 = 0; kb4 < 4; kb4++) {
#pragma unroll
            for (int jn = 0; jn < 8; jn++) {
                const int nc = jn * 8 + g;
                unsigned bf[2];
                bf[0] = ks_[nc * AP + kb4 * 8 + q4];
                bf[1] = ks_[nc * AP + kb4 * 8 + q4 + 4];
                mma16(sacc[jn], qf[kb4], bf);
            }
        }

        // Stablemax numerator -> registers (packed as GEMM2 A-fragments)
        unsigned ta[8], tb[8];
#pragma unroll
        for (int jn = 0; jn < 8; jn++) {
            const float s0 = sacc[jn][0] * 0.125f;
            const float s1 = sacc[jn][1] * 0.125f;
            const float s2 = sacc[jn][2] * 0.125f;
            const float s3 = sacc[jn][3] * 0.125f;
            const float t0 = (s0 >= 0.0f) ? (s0 + 1.0f) : __fdividef(1.0f, 1.0f - s0);
            const float t1 = (s1 >= 0.0f) ? (s1 + 1.0f) : __fdividef(1.0f, 1.0f - s1);
            const float t2 = (s2 >= 0.0f) ? (s2 + 1.0f) : __fdividef(1.0f, 1.0f - s2);
            const float t3 = (s3 >= 0.0f) ? (s3 + 1.0f) : __fdividef(1.0f, 1.0f - s3);
            dlo += t0 + t1;
            dhi += t2 + t3;
            ta[jn] = pkh2(t0, t1);
            tb[jn] = pkh2(t2, t3);
        }

        // GEMM2: O(16m x 64dv) += T V, k = 64; A straight from registers
#pragma unroll
        for (int kb = 0; kb < 4; kb++) {
            unsigned af[4] = {ta[2 * kb], tb[2 * kb], ta[2 * kb + 1], tb[2 * kb + 1]};
#pragma unroll
            for (int jd = 0; jd < 8; jd++) {
                const int dv = jd * 8 + g;
                unsigned bf[2];
                bf[0] = vs_[dv * AP + kb * 8 + q4];
                bf[1] = vs_[dv * AP + kb * 8 + q4 + 4];
                mma16(oacc[jd], af, bf);
            }
        }

        CP_WAIT0();       // next K/V landed
        __syncthreads();  // everyone done reading buffer t&1
    }

    // Row denominators: quad all-reduce (4 lanes share each row)
#pragma unroll
    for (int off = 1; off < 4; off <<= 1) {
        dlo += __shfl_xor_sync(0xffffffffu, dlo, off);
        dhi += __shfl_xor_sync(0xffffffffu, dhi, off);
    }
    const float inv_lo = 1.0f / dlo, inv_hi = 1.0f / dhi;

    // Write ctx fp16 [B,S,E]
    const int b = bh >> 4, h = bh & 15;
    const size_t base_lo = ((size_t)b * SL + q0 + r_lo) * 512 + h * 32;
    const size_t base_hi = ((size_t)b * SL + q0 + r_hi) * 512 + h * 32;
#pragma unroll
    for (int jd = 0; jd < 8; jd++) {
        ctx[base_lo + jd * 4 + q4] = pkh2(oacc[jd][0] * inv_lo, oacc[jd][1] * inv_lo);
        ctx[base_hi + jd * 4 + q4] = pkh2(oacc[jd][2] * inv_hi, oacc[jd][3] * inv_hi);
    }
}

// ---------------------------------------------------------------------------
extern "C" void kernel_launch(void* const* d_in, const int* in_sizes, int n_in,
                              void* d_out, int out_size)
{
    const float* query     = (const float*)d_in[0];
    const float* key_value = (const float*)d_in[1];
    const float* Wq = (const float*)d_in[2];
    const float* bq = (const float*)d_in[3];
    const float* Wk = (const float*)d_in[4];
    const float* bk = (const float*)d_in[5];
    const float* Wv = (const float*)d_in[6];
    const float* bv = (const float*)d_in[7];
    const float* Wo = (const float*)d_in[8];
    const float* bo = (const float*)d_in[9];
    float* out = (float*)d_out;

    unsigned *qc, *kvc, *wq, *wk, *wv, *wo, *gq, *gk, *gvt, *gctx;
    cudaGetSymbolAddress((void**)&qc,  g_qc);
    cudaGetSymbolAddress((void**)&kvc, g_kvc);
    cudaGetSymbolAddress((void**)&wq,  g_wq);
    cudaGetSymbolAddress((void**)&wk,  g_wk);
    cudaGetSymbolAddress((void**)&wv,  g_wv);
    cudaGetSymbolAddress((void**)&wo,  g_wo);
    cudaGetSymbolAddress((void**)&gq,  g_q);
    cudaGetSymbolAddress((void**)&gk,  g_k);
    cudaGetSymbolAddress((void**)&gvt, g_vt);
    cudaGetSymbolAddress((void**)&gctx, g_ctx);

    const int nBig4 = NB * SL * Eq / 4, nW4 = Eq * Eq / 4;
    cvt_f16<<<2048, 256>>>((const float4*)query,     (uint2*)qc,  nBig4);
    cvt_f16<<<2048, 256>>>((const float4*)key_value, (uint2*)kvc, nBig4);
    cvt_f16<<<1024, 256>>>((const float4*)Wq, (uint2*)wq, nW4);
    cvt_f16<<<1024, 256>>>((const float4*)Wk, (uint2*)wk, nW4);
    cvt_f16<<<1024, 256>>>((const float4*)Wv, (uint2*)wv, nW4);
    cvt_f16<<<1024, 256>>>((const float4*)Wo, (uint2*)wo, nW4);

    const dim3 gemm_grid(Eq / 128, (NB * SL) / 128);  // (8, 64)
    gemm_f16<0><<<gemm_grid, 256>>>(qc,  wq, bq, (float*)gq);
    gemm_f16<0><<<gemm_grid, 256>>>(kvc, wk, bk, (float*)gk);
    gemm_f16<2><<<gemm_grid, 256>>>(kvc, wv, bv, (float*)gvt);

    cudaFuncSetAttribute(attn_f16, cudaFuncAttributeMaxDynamicSharedMemorySize,
                         ATTN_SMEM_BYTES);
    attn_f16<<<dim3(SL / 128, NB * NH), 256, ATTN_SMEM_BYTES>>>(gq, gk, gvt, gctx);

    gemm_f16<1><<<gemm_grid, 256>>>(gctx, wo, bo, out);
}

// round 7
// speedup vs baseline: 1.0001x; 1.0001x over previous
#include <cuda_runtime.h>
#include <cuda_fp16.h>

#define Eq 1024
#define NH 16
#define DH 64
#define NB 4
#define SL 2048

// Scratch (__device__ globals; alloc-free rule). All fp16 packed as u32 pairs.
__device__ unsigned g_qc[NB * SL * Eq / 2];      // fp16(query)
__device__ unsigned g_kvc[NB * SL * Eq / 2];     // fp16(key_value)
__device__ unsigned g_wq[Eq * Eq / 2], g_wk[Eq * Eq / 2];
__device__ unsigned g_wv[Eq * Eq / 2], g_wo[Eq * Eq / 2];
__device__ unsigned g_q[NB * NH * SL * DH / 2];  // [B,H,S,HD] fp16
__device__ unsigned g_k[NB * NH * SL * DH / 2];  // [B,H,S,HD] fp16
__device__ unsigned g_vt[NB * NH * SL * DH / 2]; // [B,H,HD,S] fp16 (transposed!)
__device__ unsigned g_ctx[NB * SL * Eq / 2];     // [B,S,E] fp16

__device__ __forceinline__ unsigned pkh2(float a, float b) {
    __half2 h = __floats2half2_rn(a, b);
    return *(unsigned*)&h;
}

__device__ __forceinline__ void mma16(float* c, const unsigned* a, const unsigned* b) {
    asm volatile(
        "mma.sync.aligned.m16n8k16.row.col.f32.f16.f16.f32 "
        "{%0,%1,%2,%3}, {%4,%5,%6,%7}, {%8,%9}, {%0,%1,%2,%3};"
        : "+f"(c[0]), "+f"(c[1]), "+f"(c[2]), "+f"(c[3])
        : "r"(a[0]), "r"(a[1]), "r"(a[2]), "r"(a[3]), "r"(b[0]), "r"(b[1]));
}

__device__ __forceinline__ void cp16(unsigned smem_u32, const void* gptr) {
    asm volatile("cp.async.cg.shared.global [%0], [%1], 16;" :: "r"(smem_u32), "l"(gptr));
}
#define CP_COMMIT() asm volatile("cp.async.commit_group;")
#define CP_WAIT0()  asm volatile("cp.async.wait_group 0;")

// ---------------------------------------------------------------------------
// fp32 -> fp16-packed converter
// ---------------------------------------------------------------------------
__global__ void cvt_f16(const float4* __restrict__ src, uint2* __restrict__ dst, int n4) {
    for (int i = blockIdx.x * blockDim.x + threadIdx.x; i < n4; i += gridDim.x * blockDim.x) {
        float4 s = src[i];
        dst[i] = make_uint2(pkh2(s.x, s.y), pkh2(s.z, s.w));
    }
}

// ---------------------------------------------------------------------------
// fp16 GEMM: out = A @ W^T + bias. A,W fp16-packed u32, K-major (512 u32/row).
// 128x128x32 tile, 256 thr (8 warps 4x2), warp 32x64. cp.async 2-stage.
// MODE 0: [B,H,S,HD] fp16; MODE 1: flat fp32; MODE 2: [B,H,HD,S] fp16 transposed.
// ---------------------------------------------------------------------------
#define GP 20  // u32 pitch per row (16 used)

template <int MODE>
__global__ __launch_bounds__(256, 2) void gemm_f16(
    const unsigned* __restrict__ A, const unsigned* __restrict__ W,
    const float* __restrict__ bias, float* __restrict__ out)
{
    __shared__ unsigned As[2][128 * GP];
    __shared__ unsigned Bs[2][128 * GP];

    const int tid = threadIdx.x;
    const int m0 = blockIdx.y * 128, n0 = blockIdx.x * 128;
    const int w = tid >> 5, lane = tid & 31;
    const int wm = w >> 1, wn = w & 1;
    const int g = lane >> 2, q4 = lane & 3;

    // copy mapping: per stage per operand 512 chunks (128 rows x 4x16B)
    const int r0 = tid >> 2, r1 = r0 + 64;
    const int kq = (tid & 3) * 4;

    const unsigned sA = (unsigned)__cvta_generic_to_shared(&As[0][0]);
    const unsigned sB = (unsigned)__cvta_generic_to_shared(&Bs[0][0]);
    const unsigned stageBytes = 128 * GP * 4;

    float acc[2][8][4];
#pragma unroll
    for (int i = 0; i < 2; i++)
#pragma unroll
        for (int j = 0; j < 8; j++)
#pragma unroll
            for (int l = 0; l < 4; l++) acc[i][j][l] = 0.0f;

    auto issue = [&](int t) {
        const int s = t & 1;
        const int kb = t * 16 + kq;  // u32 col in gmem row
        cp16(sA + s * stageBytes + (r0 * GP + kq) * 4, A + (size_t)(m0 + r0) * 512 + kb);
        cp16(sA + s * stageBytes + (r1 * GP + kq) * 4, A + (size_t)(m0 + r1) * 512 + kb);
        cp16(sB + s * stageBytes + (r0 * GP + kq) * 4, W + (size_t)(n0 + r0) * 512 + kb);
        cp16(sB + s * stageBytes + (r1 * GP + kq) * 4, W + (size_t)(n0 + r1) * 512 + kb);
        CP_COMMIT();
    };

    issue(0);
    for (int t = 0; t < 32; t++) {
        CP_WAIT0();
        __syncthreads();
        if (t < 31) issue(t + 1);
        const unsigned* as = &As[t & 1][0];
        const unsigned* bs = &Bs[t & 1][0];
#pragma unroll
        for (int kb4 = 0; kb4 < 16; kb4 += 8) {  // two k16 blocks
            unsigned af[2][4], bf[8][2];
#pragma unroll
            for (int im = 0; im < 2; im++) {
                const int mr = wm * 32 + im * 16 + g;
                af[im][0] = as[mr * GP + kb4 + q4];
                af[im][1] = as[(mr + 8) * GP + kb4 + q4];
                af[im][2] = as[mr * GP + kb4 + q4 + 4];
                af[im][3] = as[(mr + 8) * GP + kb4 + q4 + 4];
            }
#pragma unroll
            for (int jn = 0; jn < 8; jn++) {
                const int nc = wn * 64 + jn * 8 + g;
                bf[jn][0] = bs[nc * GP + kb4 + q4];
                bf[jn][1] = bs[nc * GP + kb4 + q4 + 4];
            }
#pragma unroll
            for (int im = 0; im < 2; im++)
#pragma unroll
                for (int jn = 0; jn < 8; jn++)
                    mma16(acc[im][jn], af[im], bf[jn]);
        }
    }

#pragma unroll
    for (int im = 0; im < 2; im++) {
#pragma unroll
        for (int jn = 0; jn < 8; jn++) {
            const int gn = n0 + wn * 64 + jn * 8 + 2 * q4;
            const float2 bv = *(const float2*)(bias + gn);
#pragma unroll
            for (int h2 = 0; h2 < 2; h2++) {
                const int gm = m0 + wm * 32 + im * 16 + h2 * 8 + g;
                const float o0 = acc[im][jn][2 * h2] + bv.x;
                const float o1 = acc[im][jn][2 * h2 + 1] + bv.y;
                const int bb = gm >> 11, ss = gm & 2047;
                const int hh = gn >> 6, dd = gn & 63;
                if (MODE == 0) {
                    ((unsigned*)out)[(((size_t)(bb * NH + hh)) * SL + ss) * 32 + (dd >> 1)] =
                        pkh2(o0, o1);
                } else if (MODE == 2) {
                    __half* vt = (__half*)out;
                    vt[(((size_t)(bb * NH + hh)) * DH + dd) * SL + ss] = __float2half_rn(o0);
                    vt[(((size_t)(bb * NH + hh)) * DH + dd + 1) * SL + ss] = __float2half_rn(o1);
                } else {
                    *(float2*)(out + (size_t)gm * Eq + gn) = make_float2(o0, o1);
                }
            }
        }
    }
}

// ---------------------------------------------------------------------------
// Fused stablemax attention, fp16 m16n8k16, register-resident T (FA2 identity),
// register denominators, V^T gmem layout, cp.async double-buffered K/V.
// 8 warps x 16 q-rows, full n=64 per warp. One __syncthreads per kv tile.
// ---------------------------------------------------------------------------
#define AP 36  // u32 pitch for 64-half rows (32 used)
#define ATTN_SMEM_BYTES ((128 * AP + 4 * 64 * AP) * 4)

__global__ __launch_bounds__(256, 2) void attn_f16(
    const unsigned* __restrict__ qg, const unsigned* __restrict__ kg,
    const unsigned* __restrict__ vtg, unsigned* __restrict__ ctx)
{
    extern __shared__ unsigned sm[];
    unsigned* Qs = sm;                // [128][AP]
    unsigned* Ks = Qs + 128 * AP;     // [2][64][AP]
    unsigned* Vs = Ks + 2 * 64 * AP;  // [2][64][AP]  rows = dv, cols = kv halfs

    const int tid = threadIdx.x;
    const int wm = tid >> 5, lane = tid & 31;
    const int g = lane >> 2, q4 = lane & 3;
    const int bh = blockIdx.y, q0 = blockIdx.x * 128;
    const int r_lo = wm * 16 + g, r_hi = r_lo + 8;

    const unsigned* qb = qg + ((size_t)bh * SL + q0) * 32;
    const unsigned* kb = kg + (size_t)bh * SL * 32;
    const unsigned* vtb = vtg + (size_t)bh * DH * (SL / 2);  // [64 rows][1024 u32]

    const unsigned sQ = (unsigned)__cvta_generic_to_shared(Qs);
    const unsigned sK = (unsigned)__cvta_generic_to_shared(Ks);
    const unsigned sV = (unsigned)__cvta_generic_to_shared(Vs);
    const unsigned kvStage = 64 * AP * 4;

    auto issue_kv = [&](int t) {
        const int s = t & 1;
        const int kv0 = t * 64;
#pragma unroll
        for (int i = 0; i < 2; i++) {
            const int idx = tid + i * 256;  // 0..511
            const int row = idx >> 3, c = (idx & 7) * 4;
            cp16(sK + s * kvStage + (row * AP + c) * 4, kb + (size_t)(kv0 + row) * 32 + c);
            cp16(sV + s * kvStage + (row * AP + c) * 4, vtb + (size_t)row * 1024 + (kv0 >> 1) + c);
        }
        CP_COMMIT();
    };

    // Prologue: Q tile + first K/V
#pragma unroll
    for (int i = 0; i < 4; i++) {
        const int idx = tid + i * 256;  // 0..1023
        const int row = idx >> 3, c = (idx & 7) * 4;
        cp16(sQ + (row * AP + c) * 4, qb + (size_t)row * 32 + c);
    }
    issue_kv(0);
    CP_WAIT0();
    __syncthreads();

    float oacc[8][4];
#pragma unroll
    for (int j = 0; j < 8; j++)
#pragma unroll
        for (int l = 0; l < 4; l++) oacc[j][l] = 0.0f;
    float dlo = 0.0f, dhi = 0.0f;

    // Q fragments are tile-invariant: hoist
    unsigned qf[4][4];
#pragma unroll
    for (int kb4 = 0; kb4 < 4; kb4++) {
        qf[kb4][0] = Qs[r_lo * AP + kb4 * 8 + q4];
        qf[kb4][1] = Qs[r_hi * AP + kb4 * 8 + q4];
        qf[kb4][2] = Qs[r_lo * AP + kb4 * 8 + q4 + 4];
        qf[kb4][3] = Qs[r_hi * AP + kb4 * 8 + q4 + 4];
    }

    for (int t = 0; t < 32; t++) {
        const unsigned* ks_ = Ks + (t & 1) * 64 * AP;
        const unsigned* vs_ = Vs + (t & 1) * 64 * AP;
        if (t < 31) issue_kv(t + 1);

        // GEMM1: S(16m x 64n) = Q K^T, k = 64 (4 k16 blocks)
        float sacc[8][4];
#pragma unroll
        for (int j = 0; j < 8; j++)
#pragma unroll
            for (int l = 0; l < 4; l++) sacc[j][l] = 0.0f;

#pragma unroll
        for (int kb4 = 0; kb4 < 4; kb4++) {
#pragma unroll
            for (int jn = 0; jn < 8; jn++) {
                const int nc = jn * 8 + g;
                unsigned bf[2];
                bf[0] = ks_[nc * AP + kb4 * 8 + q4];
                bf[1] = ks_[nc * AP + kb4 * 8 + q4 + 4];
                mma16(sacc[jn], qf[kb4], bf);
            }
        }

        // Stablemax numerator -> registers (packed as GEMM2 A-fragments)
        unsigned ta[8], tb[8];
#pragma unroll
        for (int jn = 0; jn < 8; jn++) {
            const float s0 = sacc[jn][0] * 0.125f;
            const float s1 = sacc[jn][1] * 0.125f;
            const float s2 = sacc[jn][2] * 0.125f;
            const float s3 = sacc[jn][3] * 0.125f;
            const float t0 = (s0 >= 0.0f) ? (s0 + 1.0f) : __fdividef(1.0f, 1.0f - s0);
            const float t1 = (s1 >= 0.0f) ? (s1 + 1.0f) : __fdividef(1.0f, 1.0f - s1);
            const float t2 = (s2 >= 0.0f) ? (s2 + 1.0f) : __fdividef(1.0f, 1.0f - s2);
            const float t3 = (s3 >= 0.0f) ? (s3 + 1.0f) : __fdividef(1.0f, 1.0f - s3);
            dlo += t0 + t1;
            dhi += t2 + t3;
            ta[jn] = pkh2(t0, t1);
            tb[jn] = pkh2(t2, t3);
        }

        // GEMM2: O(16m x 64dv) += T V, k = 64; A straight from registers
#pragma unroll
        for (int kb = 0; kb < 4; kb++) {
            unsigned af[4] = {ta[2 * kb], tb[2 * kb], ta[2 * kb + 1], tb[2 * kb + 1]};
#pragma unroll
            for (int jd = 0; jd < 8; jd++) {
                const int dv = jd * 8 + g;
                unsigned bf[2];
                bf[0] = vs_[dv * AP + kb * 8 + q4];
                bf[1] = vs_[dv * AP + kb * 8 + q4 + 4];
                mma16(oacc[jd], af, bf);
            }
        }

        CP_WAIT0();       // next K/V landed
        __syncthreads();  // everyone done reading buffer t&1
    }

    // Row denominators: quad all-reduce (4 lanes share each row)
#pragma unroll
    for (int off = 1; off < 4; off <<= 1) {
        dlo += __shfl_xor_sync(0xffffffffu, dlo, off);
        dhi += __shfl_xor_sync(0xffffffffu, dhi, off);
    }
    const float inv_lo = 1.0f / dlo, inv_hi = 1.0f / dhi;

    // Write ctx fp16 [B,S,E]
    const int b = bh >> 4, h = bh & 15;
    const size_t base_lo = ((size_t)b * SL + q0 + r_lo) * 512 + h * 32;
    const size_t base_hi = ((size_t)b * SL + q0 + r_hi) * 512 + h * 32;
#pragma unroll
    for (int jd = 0; jd < 8; jd++) {
        ctx[base_lo + jd * 4 + q4] = pkh2(oacc[jd][0] * inv_lo, oacc[jd][1] * inv_lo);
        ctx[base_hi + jd * 4 + q4] = pkh2(oacc[jd][2] * inv_hi, oacc[jd][3] * inv_hi);
    }
}

// ---------------------------------------------------------------------------
extern "C" void kernel_launch(void* const* d_in, const int* in_sizes, int n_in,
                              void* d_out, int out_size)
{
    const float* query     = (const float*)d_in[0];
    const float* key_value = (const float*)d_in[1];
    const float* Wq = (const float*)d_in[2];
    const float* bq = (const float*)d_in[3];
    const float* Wk = (const float*)d_in[4];
    const float* bk = (const float*)d_in[5];
    const float* Wv = (const float*)d_in[6];
    const float* bv = (const float*)d_in[7];
    const float* Wo = (const float*)d_in[8];
    const float* bo = (const float*)d_in[9];
    float* out = (float*)d_out;

    unsigned *qc, *kvc, *wq, *wk, *wv, *wo, *gq, *gk, *gvt, *gctx;
    cudaGetSymbolAddress((void**)&qc,  g_qc);
    cudaGetSymbolAddress((void**)&kvc, g_kvc);
    cudaGetSymbolAddress((void**)&wq,  g_wq);
    cudaGetSymbolAddress((void**)&wk,  g_wk);
    cudaGetSymbolAddress((void**)&wv,  g_wv);
    cudaGetSymbolAddress((void**)&wo,  g_wo);
    cudaGetSymbolAddress((void**)&gq,  g_q);
    cudaGetSymbolAddress((void**)&gk,  g_k);
    cudaGetSymbolAddress((void**)&gvt, g_vt);
    cudaGetSymbolAddress((void**)&gctx, g_ctx);

    const int nBig4 = NB * SL * Eq / 4, nW4 = Eq * Eq / 4;
    cvt_f16<<<2048, 256>>>((const float4*)query,     (uint2*)qc,  nBig4);
    cvt_f16<<<2048, 256>>>((const float4*)key_value, (uint2*)kvc, nBig4);
    cvt_f16<<<1024, 256>>>((const float4*)Wq, (uint2*)wq, nW4);
    cvt_f16<<<1024, 256>>>((const float4*)Wk, (uint2*)wk, nW4);
    cvt_f16<<<1024, 256>>>((const float4*)Wv, (uint2*)wv, nW4);
    cvt_f16<<<1024, 256>>>((const float4*)Wo, (uint2*)wo, nW4);

    const dim3 gemm_grid(Eq / 128, (NB * SL) / 128);  // (8, 64)
    gemm_f16<0><<<gemm_grid, 256>>>(qc,  wq, bq, (float*)gq);
    gemm_f16<0><<<gemm_grid, 256>>>(kvc, wk, bk, (float*)gk);
    gemm_f16<2><<<gemm_grid, 256>>>(kvc, wv, bv, (float*)gvt);

    cudaFuncSetAttribute(attn_f16, cudaFuncAttributeMaxDynamicSharedMemorySize,
                         ATTN_SMEM_BYTES);
    attn_f16<<<dim3(SL / 128, NB * NH), 256, ATTN_SMEM_BYTES>>>(gq, gk, gvt, gctx);

    gemm_f16<1><<<gemm_grid, 256>>>(gctx, wo, bo, out);
}